// round 3
// baseline (speedup 1.0000x reference)
#include <cuda_runtime.h>
#include <cstdint>

#define N_NODES 50000
#define N_EDGES 800000
#define F 128
#define LN_EPS 1e-5f

// ---------------- scratch (__device__ globals only; no allocations) ----------------
__device__ int   g_is64;                      // 1 if edge_index is int64, 0 if int32
__device__ int   g_count[N_NODES];            // in-degree (int, deterministic)
__device__ int   g_start[N_NODES + 1];        // CSR row starts
__device__ int   g_cursor[N_NODES];           // fill cursors
__device__ int   g_esrc[N_EDGES];             // CSR: src node per edge slot
__device__ float g_invdeg[N_NODES];           // 1/max(deg,1)
__device__ float g_s[(size_t)N_NODES * F];    // per-node neighbor sums
__device__ float g_h[(size_t)N_NODES * F];    // layer-1 input
__device__ float g_o[(size_t)N_NODES * F];    // raw SAGE output (pre-LN)
__device__ float g_stats[8];                  // [sum0,sq0,m0,a0, sum1,sq1,m1,a1]

// ---------------- index load helper (dtype-agnostic) ----------------
__device__ __forceinline__ int ld_idx(const void* ei, long long pos, int is64) {
    if (is64) return (int)((const long long*)ei)[pos];
    return ((const int*)ei)[pos];
}

// ---------------- dtype probe + stats zero ----------------
__global__ void detect_kernel(const void* ei) {
    __shared__ int nz;
    int tid = threadIdx.x;
    if (tid == 0) nz = 0;
    __syncthreads();
    // If int64: every odd 32-bit word (high half of nonneg id < 2^31) is 0.
    // If int32: odd words are random node ids; all-zero across 256 samples impossible.
    int v = ((const int*)ei)[2 * tid + 1];
    if (v != 0) atomicAdd(&nz, 1);
    __syncthreads();
    if (tid == 0) g_is64 = (nz == 0) ? 1 : 0;
    if (tid < 8) g_stats[tid] = 0.0f;
}

// ---------------- zero counters ----------------
__global__ void zero_kernel() {
    int i = blockIdx.x * blockDim.x + threadIdx.x;
    if (i < N_NODES) { g_count[i] = 0; g_cursor[i] = 0; }
}

// ---------------- histogram of dst ----------------
__global__ void hist_kernel(const void* ei) {
    int e = blockIdx.x * blockDim.x + threadIdx.x;
    if (e < N_EDGES) {
        int d = ld_idx(ei, (long long)N_EDGES + e, g_is64);
        atomicAdd(&g_count[d], 1);
    }
}

// ---------------- single-block scan -> g_start, g_invdeg ----------------
__global__ void __launch_bounds__(1024) scan_kernel() {
    __shared__ int sh[1024];
    const int CHUNK = (N_NODES + 1023) / 1024;   // 49
    int t = threadIdx.x;
    int base = t * CHUNK;
    int local = 0;
    for (int i = base; i < base + CHUNK && i < N_NODES; i++) local += g_count[i];
    sh[t] = local;
    __syncthreads();
    // Hillis-Steele inclusive scan
    for (int off = 1; off < 1024; off <<= 1) {
        int v = (t >= off) ? sh[t - off] : 0;
        __syncthreads();
        sh[t] += v;
        __syncthreads();
    }
    int run = sh[t] - local;   // exclusive prefix of this chunk
    for (int i = base; i < base + CHUNK && i < N_NODES; i++) {
        g_start[i] = run;
        int c = g_count[i];
        run += c;
        g_invdeg[i] = 1.0f / fmaxf((float)c, 1.0f);
    }
    if (t == 1023) g_start[N_NODES] = sh[1023];
}

// ---------------- CSR fill ----------------
__global__ void fill_kernel(const void* ei) {
    int e = blockIdx.x * blockDim.x + threadIdx.x;
    if (e < N_EDGES) {
        int is64 = g_is64;
        int d = ld_idx(ei, (long long)N_EDGES + e, is64);
        int s = ld_idx(ei, (long long)e, is64);
        int pos = atomicAdd(&g_cursor[d], 1);
        g_esrc[g_start[d] + pos] = s;
    }
}

// ---------------- gather-sum: warp per node, 4 cols per lane ----------------
__global__ void gather_kernel(const float* __restrict__ hin) {
    const float* h = hin ? hin : (const float*)g_h;
    int n = (blockIdx.x * blockDim.x + threadIdx.x) >> 5;
    int lane = threadIdx.x & 31;
    if (n >= N_NODES) return;
    int e = g_start[n];
    int end = g_start[n + 1];
    float4 acc0 = make_float4(0.f, 0.f, 0.f, 0.f);
    float4 acc1 = make_float4(0.f, 0.f, 0.f, 0.f);
    for (; e + 1 < end; e += 2) {
        int s0 = g_esrc[e];
        int s1 = g_esrc[e + 1];
        float4 v0 = *(const float4*)(h + (size_t)s0 * F + lane * 4);
        float4 v1 = *(const float4*)(h + (size_t)s1 * F + lane * 4);
        acc0.x += v0.x; acc0.y += v0.y; acc0.z += v0.z; acc0.w += v0.w;
        acc1.x += v1.x; acc1.y += v1.y; acc1.z += v1.z; acc1.w += v1.w;
    }
    if (e < end) {
        int s0 = g_esrc[e];
        float4 v0 = *(const float4*)(h + (size_t)s0 * F + lane * 4);
        acc0.x += v0.x; acc0.y += v0.y; acc0.z += v0.z; acc0.w += v0.w;
    }
    acc0.x += acc1.x; acc0.y += acc1.y; acc0.z += acc1.z; acc0.w += acc1.w;
    *(float4*)(g_s + (size_t)n * F + lane * 4) = acc0;
}

// ---------------- fused GEMM ----------------
// MODE 0: g_o = (g_s*invdeg) @ W0^T + bias + A @ W1^T   (K=256), accumulate LN stats
// MODE 1: g_h = A @ W0^T + prelu(ln(g_o))               (K=128), skip layer
#define GM_TK 16
#define APAD 132

template<int MODE, int KT>
__global__ void __launch_bounds__(256) gemm_kernel(
    const float* __restrict__ A2,
    const float* __restrict__ W0,
    const float* __restrict__ W1,
    const float* __restrict__ bias,
    int stat_ofs,
    const float* __restrict__ lnw,
    const float* __restrict__ lnb,
    const float* __restrict__ pw)
{
    __shared__ __align__(16) float As[GM_TK][APAD];
    __shared__ __align__(16) float Bs[GM_TK][APAD];
    __shared__ float2 rbuf[256];

    const float* A = A2 ? A2 : (const float*)g_h;
    float* out = (MODE == 0) ? (float*)g_o : (float*)g_h;

    int tid = threadIdx.x;
    int row0 = blockIdx.x * 128;
    int tx = tid & 15;        // col group (8 cols each)
    int ty = tid >> 4;        // row group (8 rows each)

    float acc[8][8];
#pragma unroll
    for (int i = 0; i < 8; i++)
#pragma unroll
        for (int j = 0; j < 8; j++) acc[i][j] = 0.0f;

    for (int kt = 0; kt < KT; kt++) {
        // stage A tile: As[kk][m] = A[row0+m][kt*16+kk]
#pragma unroll
        for (int it = 0; it < 2; it++) {
            int r = (tid >> 2) + it * 64;
            int c4 = (tid & 3) * 4;
            int row = row0 + r;
            float4 v = make_float4(0.f, 0.f, 0.f, 0.f);
            if (row < N_NODES) {
                int kg = kt * GM_TK + c4;
                if (MODE == 0) {
                    if (kg < F) {
                        v = *(const float4*)(g_s + (size_t)row * F + kg);
                        float id = g_invdeg[row];
                        v.x *= id; v.y *= id; v.z *= id; v.w *= id;
                    } else {
                        v = *(const float4*)(A + (size_t)row * F + (kg - F));
                    }
                } else {
                    v = *(const float4*)(A + (size_t)row * F + kg);
                }
            }
            As[c4 + 0][r] = v.x;
            As[c4 + 1][r] = v.y;
            As[c4 + 2][r] = v.z;
            As[c4 + 3][r] = v.w;
        }
        // stage B tile: Bs[kk][j] = W[j][kc+kk]
        {
            int kk = tid & 15;
            const float* W = W0;
            int kc = kt * GM_TK;
            if (MODE == 0 && kc >= F) { W = W1; kc -= F; }
#pragma unroll
            for (int i = 0; i < 8; i++) {
                int j = (tid >> 4) + 16 * i;
                Bs[kk][j] = W[j * F + kc + kk];
            }
        }
        __syncthreads();

#pragma unroll
        for (int kk = 0; kk < GM_TK; kk++) {
            float4 a0 = *(const float4*)&As[kk][ty * 8];
            float4 a1 = *(const float4*)&As[kk][ty * 8 + 4];
            float4 b0 = *(const float4*)&Bs[kk][tx * 8];
            float4 b1 = *(const float4*)&Bs[kk][tx * 8 + 4];
            float a[8] = {a0.x, a0.y, a0.z, a0.w, a1.x, a1.y, a1.z, a1.w};
            float b[8] = {b0.x, b0.y, b0.z, b0.w, b1.x, b1.y, b1.z, b1.w};
#pragma unroll
            for (int i = 0; i < 8; i++)
#pragma unroll
                for (int j = 0; j < 8; j++)
                    acc[i][j] += a[i] * b[j];
        }
        __syncthreads();
    }

    // epilogue
    if (MODE == 0) {
        float lsum = 0.f, lsq = 0.f;
#pragma unroll
        for (int i = 0; i < 8; i++) {
            int row = row0 + ty * 8 + i;
            if (row < N_NODES) {
#pragma unroll
                for (int j = 0; j < 8; j++) {
                    float v = acc[i][j] + bias[tx * 8 + j];
                    acc[i][j] = v;
                    lsum += v;
                    lsq += v * v;
                }
                *(float4*)(out + (size_t)row * F + tx * 8) =
                    make_float4(acc[i][0], acc[i][1], acc[i][2], acc[i][3]);
                *(float4*)(out + (size_t)row * F + tx * 8 + 4) =
                    make_float4(acc[i][4], acc[i][5], acc[i][6], acc[i][7]);
            }
        }
        rbuf[tid] = make_float2(lsum, lsq);
        __syncthreads();
        for (int s2 = 128; s2 > 0; s2 >>= 1) {
            if (tid < s2) {
                rbuf[tid].x += rbuf[tid + s2].x;
                rbuf[tid].y += rbuf[tid + s2].y;
            }
            __syncthreads();
        }
        if (tid == 0) {
            atomicAdd(&g_stats[stat_ofs], rbuf[0].x);
            atomicAdd(&g_stats[stat_ofs + 1], rbuf[0].y);
        }
    } else {
        float m = g_stats[2];
        float a = g_stats[3];
        float pww = pw[0];
#pragma unroll
        for (int i = 0; i < 8; i++) {
            int row = row0 + ty * 8 + i;
            if (row < N_NODES) {
#pragma unroll
                for (int j = 0; j < 8; j++) {
                    int col = tx * 8 + j;
                    float o = g_o[(size_t)row * F + col];
                    float t = (o - m) * a * lnw[col] + lnb[col];
                    t = (t >= 0.f) ? t : pww * t;
                    acc[i][j] += t;
                }
                *(float4*)(out + (size_t)row * F + tx * 8) =
                    make_float4(acc[i][0], acc[i][1], acc[i][2], acc[i][3]);
                *(float4*)(out + (size_t)row * F + tx * 8 + 4) =
                    make_float4(acc[i][4], acc[i][5], acc[i][6], acc[i][7]);
            }
        }
    }
}

// ---------------- LN-stats finalize ----------------
__global__ void finalize_kernel(int ofs) {
    float S = g_stats[ofs], SS = g_stats[ofs + 1];
    float inv = 1.0f / ((float)N_NODES * (float)F);
    float m = S * inv;
    float var = fmaxf(SS * inv - m * m, 0.0f);
    g_stats[ofs + 2] = m;
    g_stats[ofs + 3] = 1.0f / (sqrtf(var) + LN_EPS);
}

// ---------------- final LN + PReLU ----------------
__global__ void apply_kernel(const float* __restrict__ lnw,
                             const float* __restrict__ lnb,
                             const float* __restrict__ pw,
                             float* __restrict__ out) {
    int i = blockIdx.x * blockDim.x + threadIdx.x;
    if (i < N_NODES * F) {
        float m = g_stats[6];
        float a = g_stats[7];
        int col = i & (F - 1);
        float t = (g_o[i] - m) * a * lnw[col] + lnb[col];
        out[i] = (t >= 0.f) ? t : pw[0] * t;
    }
}

// ---------------- launch (pure kernel launches; graph-capturable) ----------------
extern "C" void kernel_launch(void* const* d_in, const int* in_sizes, int n_in,
                              void* d_out, int out_size) {
    const float* x      = (const float*)d_in[0];
    const void*  ei     = d_in[1];
    const float* Wl0    = (const float*)d_in[2];
    const float* bl0    = (const float*)d_in[3];
    const float* Wr0    = (const float*)d_in[4];
    const float* lnw0   = (const float*)d_in[5];
    const float* lnb0   = (const float*)d_in[6];
    const float* pw0    = (const float*)d_in[7];
    const float* skipW0 = (const float*)d_in[8];
    const float* Wl1    = (const float*)d_in[9];
    const float* bl1    = (const float*)d_in[10];
    const float* Wr1    = (const float*)d_in[11];
    const float* lnw1   = (const float*)d_in[12];
    const float* lnb1   = (const float*)d_in[13];
    const float* pw1    = (const float*)d_in[14];

    int gblocks = (N_NODES + 127) / 128;                 // 391
    int eblocks = (N_EDGES + 255) / 256;                 // 3125
    int nblocks = (N_NODES + 255) / 256;                 // 196
    int wblocks = (N_NODES * 32 + 255) / 256;            // 6250

    // CSR build (once; reused by both layers)
    detect_kernel<<<1, 256>>>(ei);
    zero_kernel<<<nblocks, 256>>>();
    hist_kernel<<<eblocks, 256>>>(ei);
    scan_kernel<<<1, 1024>>>();
    fill_kernel<<<eblocks, 256>>>(ei);

    // layer 0
    gather_kernel<<<wblocks, 256>>>(x);
    gemm_kernel<0, 16><<<gblocks, 256>>>(x, Wl0, Wr0, bl0, 0,
                                         nullptr, nullptr, nullptr);
    finalize_kernel<<<1, 1>>>(0);

    // h = x @ skipW0^T + prelu(ln(out0))  -> g_h
    gemm_kernel<1, 8><<<gblocks, 256>>>(x, skipW0, nullptr, nullptr, 0,
                                        lnw0, lnb0, pw0);

    // layer 1
    gather_kernel<<<wblocks, 256>>>(nullptr);            // reads g_h
    gemm_kernel<0, 16><<<gblocks, 256>>>(nullptr, Wl1, Wr1, bl1, 4,
                                         nullptr, nullptr, nullptr);
    finalize_kernel<<<1, 1>>>(4);

    apply_kernel<<<(N_NODES * F + 255) / 256, 256>>>(lnw1, lnb1, pw1, (float*)d_out);
}

// round 4
// speedup vs baseline: 1.3734x; 1.3734x over previous
#include <cuda_runtime.h>
#include <cstdint>

#define N_NODES 50000
#define N_EDGES 800000
#define F 128
#define LN_EPS 1e-5f
#define NBLK 196   // (N_NODES+255)/256

// ---------------- scratch (__device__ globals only; no allocations) ----------------
__device__ int   g_is64;
__device__ int   g_count[N_NODES];
__device__ int   g_start[N_NODES + 1];
__device__ int   g_cursor[N_NODES];
__device__ int   g_bsum[NBLK];
__device__ int   g_boff[NBLK];
__device__ int   g_esrc[N_EDGES];
__device__ float g_invdeg[N_NODES];
__device__ float g_s[(size_t)N_NODES * F];
__device__ float g_h[(size_t)N_NODES * F];
__device__ float g_o[(size_t)N_NODES * F];
__device__ float g_stats[8];

// ---------------- packed fp32x2 helpers (sm_103a FFMA2 path) ----------------
__device__ __forceinline__ unsigned long long pk2(float lo, float hi) {
    unsigned long long r;
    asm("mov.b64 %0, {%1, %2};" : "=l"(r) : "f"(lo), "f"(hi));
    return r;
}
__device__ __forceinline__ void upk2(float& lo, float& hi, unsigned long long v) {
    asm("mov.b64 {%0, %1}, %2;" : "=f"(lo), "=f"(hi) : "l"(v));
}
__device__ __forceinline__ void ffma2(unsigned long long& acc,
                                      unsigned long long a, unsigned long long b) {
    asm("fma.rn.f32x2 %0, %1, %2, %0;" : "+l"(acc) : "l"(a), "l"(b));
}

// ---------------- index load helper (dtype-agnostic) ----------------
__device__ __forceinline__ int ld_idx(const void* ei, long long pos, int is64) {
    if (is64) return (int)((const long long*)ei)[pos];
    return ((const int*)ei)[pos];
}

// ---------------- dtype probe + stats zero ----------------
__global__ void detect_kernel(const void* ei) {
    __shared__ int nz;
    int tid = threadIdx.x;
    if (tid == 0) nz = 0;
    __syncthreads();
    int v = ((const int*)ei)[2 * tid + 1];
    if (v != 0) atomicAdd(&nz, 1);
    __syncthreads();
    if (tid == 0) g_is64 = (nz == 0) ? 1 : 0;
    if (tid < 8) g_stats[tid] = 0.0f;
}

// ---------------- zero counters ----------------
__global__ void zero_kernel() {
    int i = blockIdx.x * blockDim.x + threadIdx.x;
    if (i < N_NODES) { g_count[i] = 0; g_cursor[i] = 0; }
}

// ---------------- histogram of dst ----------------
__global__ void hist_kernel(const void* ei) {
    int e = blockIdx.x * blockDim.x + threadIdx.x;
    if (e < N_EDGES) {
        int d = ld_idx(ei, (long long)N_EDGES + e, g_is64);
        atomicAdd(&g_count[d], 1);
    }
}

// ---------------- multi-block scan: A(block sums) -> B(scan sums) -> C(final) ----
__global__ void scanA_kernel() {
    __shared__ int sh[256];
    int i = blockIdx.x * 256 + threadIdx.x;
    int c = (i < N_NODES) ? g_count[i] : 0;
    sh[threadIdx.x] = c;
    __syncthreads();
#pragma unroll
    for (int s = 128; s > 0; s >>= 1) {
        if (threadIdx.x < s) sh[threadIdx.x] += sh[threadIdx.x + s];
        __syncthreads();
    }
    if (threadIdx.x == 0) g_bsum[blockIdx.x] = sh[0];
}

__global__ void scanB_kernel() {
    __shared__ int sh[256];
    int t = threadIdx.x;
    int v = (t < NBLK) ? g_bsum[t] : 0;
    sh[t] = v;
    __syncthreads();
#pragma unroll
    for (int off = 1; off < 256; off <<= 1) {
        int u = (t >= off) ? sh[t - off] : 0;
        __syncthreads();
        sh[t] += u;
        __syncthreads();
    }
    if (t < NBLK) g_boff[t] = sh[t] - v;   // exclusive
    if (t == 0) g_start[N_NODES] = N_EDGES;
}

__global__ void scanC_kernel() {
    __shared__ int sh[256];
    int t = threadIdx.x;
    int i = blockIdx.x * 256 + t;
    int c = (i < N_NODES) ? g_count[i] : 0;
    sh[t] = c;
    __syncthreads();
#pragma unroll
    for (int off = 1; off < 256; off <<= 1) {
        int u = (t >= off) ? sh[t - off] : 0;
        __syncthreads();
        sh[t] += u;
        __syncthreads();
    }
    if (i < N_NODES) {
        g_start[i] = sh[t] - c + g_boff[blockIdx.x];
        g_invdeg[i] = 1.0f / fmaxf((float)c, 1.0f);
    }
}

// ---------------- CSR fill ----------------
__global__ void fill_kernel(const void* ei) {
    int e = blockIdx.x * blockDim.x + threadIdx.x;
    if (e < N_EDGES) {
        int is64 = g_is64;
        int d = ld_idx(ei, (long long)N_EDGES + e, is64);
        int s = ld_idx(ei, (long long)e, is64);
        int pos = atomicAdd(&g_cursor[d], 1);
        g_esrc[g_start[d] + pos] = s;
    }
}

// ---------------- gather-sum: warp per node, 4 cols per lane ----------------
__global__ void gather_kernel(const float* __restrict__ hin) {
    const float* h = hin ? hin : (const float*)g_h;
    int n = (blockIdx.x * blockDim.x + threadIdx.x) >> 5;
    int lane = threadIdx.x & 31;
    if (n >= N_NODES) return;
    int e = g_start[n];
    int end = g_start[n + 1];
    float4 acc0 = make_float4(0.f, 0.f, 0.f, 0.f);
    float4 acc1 = make_float4(0.f, 0.f, 0.f, 0.f);
    for (; e + 1 < end; e += 2) {
        int s0 = g_esrc[e];
        int s1 = g_esrc[e + 1];
        float4 v0 = *(const float4*)(h + (size_t)s0 * F + lane * 4);
        float4 v1 = *(const float4*)(h + (size_t)s1 * F + lane * 4);
        acc0.x += v0.x; acc0.y += v0.y; acc0.z += v0.z; acc0.w += v0.w;
        acc1.x += v1.x; acc1.y += v1.y; acc1.z += v1.z; acc1.w += v1.w;
    }
    if (e < end) {
        int s0 = g_esrc[e];
        float4 v0 = *(const float4*)(h + (size_t)s0 * F + lane * 4);
        acc0.x += v0.x; acc0.y += v0.y; acc0.z += v0.z; acc0.w += v0.w;
    }
    acc0.x += acc1.x; acc0.y += acc1.y; acc0.z += acc1.z; acc0.w += acc1.w;
    *(float4*)(g_s + (size_t)n * F + lane * 4) = acc0;
}

// ---------------- fused GEMM (packed f32x2 mainloop) ----------------
// MODE 0: g_o = (g_s*invdeg) @ W0^T + bias + A @ W1^T   (K=256), accumulate LN stats
// MODE 1: g_h = A @ W0^T + prelu(ln(g_o))               (K=128), skip layer
#define GM_TK 16
#define APAD 132

template<int MODE, int KT>
__global__ void __launch_bounds__(256, 2) gemm_kernel(
    const float* __restrict__ A2,
    const float* __restrict__ W0,
    const float* __restrict__ W1,
    const float* __restrict__ bias,
    int stat_ofs,
    const float* __restrict__ lnw,
    const float* __restrict__ lnb,
    const float* __restrict__ pw)
{
    __shared__ __align__(16) float As[GM_TK][APAD];
    __shared__ __align__(16) float Bs[GM_TK][APAD];
    __shared__ float2 rbuf[256];

    const float* A = A2 ? A2 : (const float*)g_h;
    float* out = (MODE == 0) ? (float*)g_o : (float*)g_h;

    int tid = threadIdx.x;
    int row0 = blockIdx.x * 128;
    int tx = tid & 15;        // col group (8 cols each)
    int ty = tid >> 4;        // row group (8 rows each)

    unsigned long long acc2[8][4];   // [row][col-pair], each packs 2 fp32
#pragma unroll
    for (int i = 0; i < 8; i++)
#pragma unroll
        for (int j = 0; j < 4; j++) acc2[i][j] = 0ULL;

    for (int kt = 0; kt < KT; kt++) {
        // stage A tile: As[kk][m] = A[row0+m][kt*16+kk]
#pragma unroll
        for (int it = 0; it < 2; it++) {
            int r = (tid >> 2) + it * 64;
            int c4 = (tid & 3) * 4;
            int row = row0 + r;
            float4 v = make_float4(0.f, 0.f, 0.f, 0.f);
            if (row < N_NODES) {
                int kg = kt * GM_TK + c4;
                if (MODE == 0) {
                    if (kg < F) {
                        v = *(const float4*)(g_s + (size_t)row * F + kg);
                        float id = g_invdeg[row];
                        v.x *= id; v.y *= id; v.z *= id; v.w *= id;
                    } else {
                        v = *(const float4*)(A + (size_t)row * F + (kg - F));
                    }
                } else {
                    v = *(const float4*)(A + (size_t)row * F + kg);
                }
            }
            As[c4 + 0][r] = v.x;
            As[c4 + 1][r] = v.y;
            As[c4 + 2][r] = v.z;
            As[c4 + 3][r] = v.w;
        }
        // stage B tile: Bs[kk][j] = W[j][kc+kk]
        {
            int kk = tid & 15;
            const float* W = W0;
            int kc = kt * GM_TK;
            if (MODE == 0 && kc >= F) { W = W1; kc -= F; }
#pragma unroll
            for (int i = 0; i < 8; i++) {
                int j = (tid >> 4) + 16 * i;
                Bs[kk][j] = W[j * F + kc + kk];
            }
        }
        __syncthreads();

#pragma unroll
        for (int kk = 0; kk < GM_TK; kk++) {
            float4 a0 = *(const float4*)&As[kk][ty * 8];
            float4 a1 = *(const float4*)&As[kk][ty * 8 + 4];
            float4 b0 = *(const float4*)&Bs[kk][tx * 8];
            float4 b1 = *(const float4*)&Bs[kk][tx * 8 + 4];
            unsigned long long b2[4];
            b2[0] = pk2(b0.x, b0.y);
            b2[1] = pk2(b0.z, b0.w);
            b2[2] = pk2(b1.x, b1.y);
            b2[3] = pk2(b1.z, b1.w);
            float a[8] = {a0.x, a0.y, a0.z, a0.w, a1.x, a1.y, a1.z, a1.w};
#pragma unroll
            for (int i = 0; i < 8; i++) {
                unsigned long long av = pk2(a[i], a[i]);
                ffma2(acc2[i][0], av, b2[0]);
                ffma2(acc2[i][1], av, b2[1]);
                ffma2(acc2[i][2], av, b2[2]);
                ffma2(acc2[i][3], av, b2[3]);
            }
        }
        __syncthreads();
    }

    // unpack accumulators
    float acc[8][8];
#pragma unroll
    for (int i = 0; i < 8; i++)
#pragma unroll
        for (int j = 0; j < 4; j++)
            upk2(acc[i][2 * j], acc[i][2 * j + 1], acc2[i][j]);

    // epilogue
    if (MODE == 0) {
        float lsum = 0.f, lsq = 0.f;
#pragma unroll
        for (int i = 0; i < 8; i++) {
            int row = row0 + ty * 8 + i;
            if (row < N_NODES) {
#pragma unroll
                for (int j = 0; j < 8; j++) {
                    float v = acc[i][j] + bias[tx * 8 + j];
                    acc[i][j] = v;
                    lsum += v;
                    lsq += v * v;
                }
                *(float4*)(out + (size_t)row * F + tx * 8) =
                    make_float4(acc[i][0], acc[i][1], acc[i][2], acc[i][3]);
                *(float4*)(out + (size_t)row * F + tx * 8 + 4) =
                    make_float4(acc[i][4], acc[i][5], acc[i][6], acc[i][7]);
            }
        }
        rbuf[tid] = make_float2(lsum, lsq);
        __syncthreads();
        for (int s2 = 128; s2 > 0; s2 >>= 1) {
            if (tid < s2) {
                rbuf[tid].x += rbuf[tid + s2].x;
                rbuf[tid].y += rbuf[tid + s2].y;
            }
            __syncthreads();
        }
        if (tid == 0) {
            atomicAdd(&g_stats[stat_ofs], rbuf[0].x);
            atomicAdd(&g_stats[stat_ofs + 1], rbuf[0].y);
        }
    } else {
        float m = g_stats[2];
        float a = g_stats[3];
        float pww = pw[0];
#pragma unroll
        for (int i = 0; i < 8; i++) {
            int row = row0 + ty * 8 + i;
            if (row < N_NODES) {
#pragma unroll
                for (int j = 0; j < 8; j++) {
                    int col = tx * 8 + j;
                    float o = g_o[(size_t)row * F + col];
                    float t = (o - m) * a * lnw[col] + lnb[col];
                    t = (t >= 0.f) ? t : pww * t;
                    acc[i][j] += t;
                }
                *(float4*)(out + (size_t)row * F + tx * 8) =
                    make_float4(acc[i][0], acc[i][1], acc[i][2], acc[i][3]);
                *(float4*)(out + (size_t)row * F + tx * 8 + 4) =
                    make_float4(acc[i][4], acc[i][5], acc[i][6], acc[i][7]);
            }
        }
    }
}

// ---------------- LN-stats finalize ----------------
__global__ void finalize_kernel(int ofs) {
    float S = g_stats[ofs], SS = g_stats[ofs + 1];
    float inv = 1.0f / ((float)N_NODES * (float)F);
    float m = S * inv;
    float var = fmaxf(SS * inv - m * m, 0.0f);
    g_stats[ofs + 2] = m;
    g_stats[ofs + 3] = 1.0f / (sqrtf(var) + LN_EPS);
}

// ---------------- final LN + PReLU ----------------
__global__ void apply_kernel(const float* __restrict__ lnw,
                             const float* __restrict__ lnb,
                             const float* __restrict__ pw,
                             float* __restrict__ out) {
    int i = blockIdx.x * blockDim.x + threadIdx.x;
    if (i < N_NODES * F) {
        float m = g_stats[6];
        float a = g_stats[7];
        int col = i & (F - 1);
        float t = (g_o[i] - m) * a * lnw[col] + lnb[col];
        out[i] = (t >= 0.f) ? t : pw[0] * t;
    }
}

// ---------------- launch (pure kernel launches; graph-capturable) ----------------
extern "C" void kernel_launch(void* const* d_in, const int* in_sizes, int n_in,
                              void* d_out, int out_size) {
    const float* x      = (const float*)d_in[0];
    const void*  ei     = d_in[1];
    const float* Wl0    = (const float*)d_in[2];
    const float* bl0    = (const float*)d_in[3];
    const float* Wr0    = (const float*)d_in[4];
    const float* lnw0   = (const float*)d_in[5];
    const float* lnb0   = (const float*)d_in[6];
    const float* pw0    = (const float*)d_in[7];
    const float* skipW0 = (const float*)d_in[8];
    const float* Wl1    = (const float*)d_in[9];
    const float* bl1    = (const float*)d_in[10];
    const float* Wr1    = (const float*)d_in[11];
    const float* lnw1   = (const float*)d_in[12];
    const float* lnb1   = (const float*)d_in[13];
    const float* pw1    = (const float*)d_in[14];

    int gblocks = (N_NODES + 127) / 128;                 // 391
    int eblocks = (N_EDGES + 255) / 256;                 // 3125
    int wblocks = (N_NODES * 32 + 255) / 256;            // 6250

    // CSR build (once; reused by both layers)
    detect_kernel<<<1, 256>>>(ei);
    zero_kernel<<<NBLK, 256>>>();
    hist_kernel<<<eblocks, 256>>>(ei);
    scanA_kernel<<<NBLK, 256>>>();
    scanB_kernel<<<1, 256>>>();
    scanC_kernel<<<NBLK, 256>>>();
    fill_kernel<<<eblocks, 256>>>(ei);

    // layer 0
    gather_kernel<<<wblocks, 256>>>(x);
    gemm_kernel<0, 16><<<gblocks, 256>>>(x, Wl0, Wr0, bl0, 0,
                                         nullptr, nullptr, nullptr);
    finalize_kernel<<<1, 1>>>(0);

    // h = x @ skipW0^T + prelu(ln(out0))  -> g_h
    gemm_kernel<1, 8><<<gblocks, 256>>>(x, skipW0, nullptr, nullptr, 0,
                                        lnw0, lnb0, pw0);

    // layer 1
    gather_kernel<<<wblocks, 256>>>(nullptr);            // reads g_h
    gemm_kernel<0, 16><<<gblocks, 256>>>(nullptr, Wl1, Wr1, bl1, 4,
                                         nullptr, nullptr, nullptr);
    finalize_kernel<<<1, 1>>>(4);

    apply_kernel<<<(N_NODES * F + 255) / 256, 256>>>(lnw1, lnb1, pw1, (float*)d_out);
}

// round 6
// speedup vs baseline: 1.9845x; 1.4449x over previous
#include <cuda_runtime.h>
#include <cuda_bf16.h>
#include <cstdint>

#define N_NODES 50000
#define N_EDGES 800000
#define F 128
#define LN_EPS 1e-5f
#define NBLK 196   // (N_NODES+255)/256

// ---------------- scratch (__device__ globals only) ----------------
__device__ int   g_is64;
__device__ int   g_count[N_NODES];
__device__ int   g_start[N_NODES + 1];
__device__ int   g_cursor[N_NODES];
__device__ int   g_bsum[NBLK];
__device__ int   g_boff[NBLK];
__device__ int   g_esrc[N_EDGES];
__device__ float g_invdeg[N_NODES];
__device__ float g_s[(size_t)N_NODES * F];
__device__ float g_h[(size_t)N_NODES * F];
__device__ float g_o[(size_t)N_NODES * F];
__device__ float g_stats[8];

// ---------------- helpers ----------------
__device__ __forceinline__ uint32_t s2u(const void* p) {
    uint32_t a;
    asm("{ .reg .u64 t; cvta.to.shared.u64 t, %1; cvt.u32.u64 %0, t; }"
        : "=r"(a) : "l"(p));
    return a;
}
// pack two fp32 -> bf16x2 (a in low half, b in high half), round-to-nearest
__device__ __forceinline__ uint32_t pkbf(float a, float b) {
    uint32_t r;
    asm("cvt.rn.bf16x2.f32 %0, %1, %2;" : "=r"(r) : "f"(b), "f"(a));
    return r;
}
__device__ __forceinline__ void ldsm4(uint32_t addr, uint32_t* r) {
    asm volatile("ldmatrix.sync.aligned.m8n8.x4.shared.b16 {%0,%1,%2,%3}, [%4];"
                 : "=r"(r[0]), "=r"(r[1]), "=r"(r[2]), "=r"(r[3]) : "r"(addr));
}
__device__ __forceinline__ void bmma(float* d, const uint32_t* a, uint32_t b0, uint32_t b1) {
    asm volatile("mma.sync.aligned.m16n8k16.row.col.f32.bf16.bf16.f32 "
                 "{%0,%1,%2,%3}, {%4,%5,%6,%7}, {%8,%9}, {%0,%1,%2,%3};"
                 : "+f"(d[0]), "+f"(d[1]), "+f"(d[2]), "+f"(d[3])
                 : "r"(a[0]), "r"(a[1]), "r"(a[2]), "r"(a[3]), "r"(b0), "r"(b1));
}

// ---------------- index load helper ----------------
__device__ __forceinline__ int ld_idx(const void* ei, long long pos, int is64) {
    if (is64) return (int)((const long long*)ei)[pos];
    return ((const int*)ei)[pos];
}

// ---------------- dtype probe + stats zero ----------------
__global__ void detect_kernel(const void* ei) {
    __shared__ int nz;
    int tid = threadIdx.x;
    if (tid == 0) nz = 0;
    __syncthreads();
    int v = ((const int*)ei)[2 * tid + 1];
    if (v != 0) atomicAdd(&nz, 1);
    __syncthreads();
    if (tid == 0) g_is64 = (nz == 0) ? 1 : 0;
    if (tid < 8) g_stats[tid] = 0.0f;
}

__global__ void zero_kernel() {
    int i = blockIdx.x * blockDim.x + threadIdx.x;
    if (i < N_NODES) { g_count[i] = 0; g_cursor[i] = 0; }
}

__global__ void hist_kernel(const void* ei) {
    int e = blockIdx.x * blockDim.x + threadIdx.x;
    if (e < N_EDGES) {
        int d = ld_idx(ei, (long long)N_EDGES + e, g_is64);
        atomicAdd(&g_count[d], 1);
    }
}

// ---------------- multi-block scan ----------------
__global__ void scanA_kernel() {
    __shared__ int sh[256];
    int i = blockIdx.x * 256 + threadIdx.x;
    int c = (i < N_NODES) ? g_count[i] : 0;
    sh[threadIdx.x] = c;
    __syncthreads();
#pragma unroll
    for (int s = 128; s > 0; s >>= 1) {
        if (threadIdx.x < s) sh[threadIdx.x] += sh[threadIdx.x + s];
        __syncthreads();
    }
    if (threadIdx.x == 0) g_bsum[blockIdx.x] = sh[0];
}

__global__ void scanB_kernel() {
    __shared__ int sh[256];
    int t = threadIdx.x;
    int v = (t < NBLK) ? g_bsum[t] : 0;
    sh[t] = v;
    __syncthreads();
#pragma unroll
    for (int off = 1; off < 256; off <<= 1) {
        int u = (t >= off) ? sh[t - off] : 0;
        __syncthreads();
        sh[t] += u;
        __syncthreads();
    }
    if (t < NBLK) g_boff[t] = sh[t] - v;
    if (t == 0) g_start[N_NODES] = N_EDGES;
}

__global__ void scanC_kernel() {
    __shared__ int sh[256];
    int t = threadIdx.x;
    int i = blockIdx.x * 256 + t;
    int c = (i < N_NODES) ? g_count[i] : 0;
    sh[t] = c;
    __syncthreads();
#pragma unroll
    for (int off = 1; off < 256; off <<= 1) {
        int u = (t >= off) ? sh[t - off] : 0;
        __syncthreads();
        sh[t] += u;
        __syncthreads();
    }
    if (i < N_NODES) {
        g_start[i] = sh[t] - c + g_boff[blockIdx.x];
        g_invdeg[i] = 1.0f / fmaxf((float)c, 1.0f);
    }
}

__global__ void fill_kernel(const void* ei) {
    int e = blockIdx.x * blockDim.x + threadIdx.x;
    if (e < N_EDGES) {
        int is64 = g_is64;
        int d = ld_idx(ei, (long long)N_EDGES + e, is64);
        int s = ld_idx(ei, (long long)e, is64);
        int pos = atomicAdd(&g_cursor[d], 1);
        g_esrc[g_start[d] + pos] = s;
    }
}

// ---------------- gather-sum: warp per node ----------------
__global__ void gather_kernel(const float* __restrict__ hin) {
    const float* h = hin ? hin : (const float*)g_h;
    int n = (blockIdx.x * blockDim.x + threadIdx.x) >> 5;
    int lane = threadIdx.x & 31;
    if (n >= N_NODES) return;
    int e = g_start[n];
    int end = g_start[n + 1];
    float4 acc0 = make_float4(0.f, 0.f, 0.f, 0.f);
    float4 acc1 = make_float4(0.f, 0.f, 0.f, 0.f);
    for (; e + 1 < end; e += 2) {
        int s0 = g_esrc[e];
        int s1 = g_esrc[e + 1];
        float4 v0 = *(const float4*)(h + (size_t)s0 * F + lane * 4);
        float4 v1 = *(const float4*)(h + (size_t)s1 * F + lane * 4);
        acc0.x += v0.x; acc0.y += v0.y; acc0.z += v0.z; acc0.w += v0.w;
        acc1.x += v1.x; acc1.y += v1.y; acc1.z += v1.z; acc1.w += v1.w;
    }
    if (e < end) {
        int s0 = g_esrc[e];
        float4 v0 = *(const float4*)(h + (size_t)s0 * F + lane * 4);
        acc0.x += v0.x; acc0.y += v0.y; acc0.z += v0.z; acc0.w += v0.w;
    }
    acc0.x += acc1.x; acc0.y += acc1.y; acc0.z += acc1.z; acc0.w += acc1.w;
    *(float4*)(g_s + (size_t)n * F + lane * 4) = acc0;
}

// ---------------- mma.sync split-bf16 fused GEMM ----------------
// MODE 0: g_o = (g_s*invdeg)@W0^T + bias + A@W1^T  (K=256, KT=16 chunks) + LN stats
// MODE 1: g_h = A@W0^T + prelu(ln(g_o))            (K=128, KT=8)
// CTA: 512 thr, tile 128x128. Warp 32x32 (2 m-tiles x 4 n-tiles m16n8k16).
// SMEM row pitch 80B: [hi bf16 k0..15 | lo bf16 k0..15 | 16B pad]; conflict-free ldmatrix.
// D = Ahi*Bhi + Ahi*Blo + Alo*Bhi   (fp32 register accumulators)
#define PITCHB 80

template<int MODE, int KT>
__global__ void __launch_bounds__(512) mmagemm_kernel(
    const float* __restrict__ A2,
    const float* __restrict__ W0,
    const float* __restrict__ W1,
    const float* __restrict__ bias,
    int stat_ofs,
    const float* __restrict__ lnw,
    const float* __restrict__ lnb,
    const float* __restrict__ pw)
{
    __shared__ __align__(16) char smA[2][128 * PITCHB];
    __shared__ __align__(16) char smB[2][128 * PITCHB];
    __shared__ float sparam[2 * F];
    __shared__ float2 rbuf[512];

    const float* A = A2 ? A2 : (const float*)g_h;
    float* out = (MODE == 0) ? (float*)g_o : (float*)g_h;

    int tid = threadIdx.x;
    int lane = tid & 31;
    int w = tid >> 5;                 // 0..15
    int row0 = blockIdx.x * 128;

    if (tid < F) {
        if (MODE == 0) sparam[tid] = bias[tid];
        else { sparam[tid] = lnw[tid]; sparam[F + tid] = lnb[tid]; }
    }

    int srow = tid >> 2;              // staging row / weight row: 0..127
    int q = tid & 3;                  // k-quad within chunk
    int grow = row0 + srow;
    bool rv = grow < N_NODES;
    float id = 1.0f;
    if (MODE == 0 && rv) id = g_invdeg[grow];

    float acc[2][4][4];
#pragma unroll
    for (int i = 0; i < 2; i++)
#pragma unroll
        for (int j = 0; j < 4; j++)
#pragma unroll
            for (int k = 0; k < 4; k++) acc[i][j][k] = 0.0f;

    float4 av, bv;

    // ---- staging: load gmem regs for chunk c ----
#define LDREGS(c)                                                              \
    {                                                                          \
        int kg = (c) * 16 + q * 4;                                             \
        float mul = 1.0f;                                                      \
        const float* ap;                                                       \
        if (MODE == 0) {                                                       \
            if (kg < F) { ap = g_s + (size_t)grow * F + kg; mul = id; }        \
            else        { ap = A + (size_t)grow * F + (kg - F); }              \
        } else {                                                               \
            ap = A + (size_t)grow * F + kg;                                    \
        }                                                                      \
        av = make_float4(0.f, 0.f, 0.f, 0.f);                                  \
        if (rv) { av = *(const float4*)ap;                                     \
                  av.x *= mul; av.y *= mul; av.z *= mul; av.w *= mul; }        \
        const float* bp = (MODE == 0 && kg >= F)                               \
                            ? (W1 + (size_t)srow * F + (kg - F))               \
                            : (W0 + (size_t)srow * F + kg);                    \
        bv = *(const float4*)bp;                                               \
    }

    // ---- staging: split + store to buffer b ----
#define STORE(b)                                                               \
    {                                                                          \
        float h0 = __bfloat162float(__float2bfloat16_rn(av.x));                \
        float h1 = __bfloat162float(__float2bfloat16_rn(av.y));                \
        float h2 = __bfloat162float(__float2bfloat16_rn(av.z));                \
        float h3 = __bfloat162float(__float2bfloat16_rn(av.w));                \
        char* ab = smA[b] + srow * PITCHB + q * 8;                             \
        *(uint2*)ab        = make_uint2(pkbf(h0, h1), pkbf(h2, h3));           \
        *(uint2*)(ab + 32) = make_uint2(pkbf(av.x - h0, av.y - h1),            \
                                        pkbf(av.z - h2, av.w - h3));           \
        float g0 = __bfloat162float(__float2bfloat16_rn(bv.x));                \
        float g1 = __bfloat162float(__float2bfloat16_rn(bv.y));                \
        float g2 = __bfloat162float(__float2bfloat16_rn(bv.z));                \
        float g3 = __bfloat162float(__float2bfloat16_rn(bv.w));                \
        char* bb = smB[b] + srow * PITCHB + q * 8;                             \
        *(uint2*)bb        = make_uint2(pkbf(g0, g1), pkbf(g2, g3));           \
        *(uint2*)(bb + 32) = make_uint2(pkbf(bv.x - g0, bv.y - g1),            \
                                        pkbf(bv.z - g2, bv.w - g3));           \
    }

    LDREGS(0);
    STORE(0);
    __syncthreads();

    int wm = w >> 2, wn = w & 3;
    int m0 = wm * 32, n0 = wn * 32;
    uint32_t rsel = (uint32_t)(lane & 15);
    uint32_t kb = (uint32_t)((lane >> 4) * 16);    // k-half byte offset

    for (int c = 0; c < KT; c++) {
        if (c + 1 < KT) LDREGS(c + 1);

        // ---- compute chunk c ----
        int b = c & 1;
        uint32_t Ab = s2u(smA[b]);
        uint32_t Bb = s2u(smB[b]);
        uint32_t aaddr0 = Ab + (m0 + rsel) * PITCHB + kb;
        uint32_t aaddr1 = aaddr0 + 16 * PITCHB;
        uint32_t baddr0 = Bb + (n0 + rsel) * PITCHB + kb;
        uint32_t baddr1 = baddr0 + 16 * PITCHB;

        uint32_t ahi[2][4], alo[2][4], bhi[2][4], blo[2][4];
        ldsm4(aaddr0, ahi[0]);  ldsm4(aaddr1, ahi[1]);
        ldsm4(baddr0, bhi[0]);  ldsm4(baddr1, bhi[1]);
        ldsm4(aaddr0 + 32, alo[0]);  ldsm4(aaddr1 + 32, alo[1]);
        ldsm4(baddr0 + 32, blo[0]);  ldsm4(baddr1 + 32, blo[1]);

        // B tile nt (0..3): group = nt>>1, idx = nt&1 -> {grp[idx], grp[idx+2]}
#pragma unroll
        for (int mt = 0; mt < 2; mt++)
#pragma unroll
            for (int nt = 0; nt < 4; nt++)
                bmma(acc[mt][nt], ahi[mt], bhi[nt >> 1][nt & 1], bhi[nt >> 1][(nt & 1) + 2]);
#pragma unroll
        for (int mt = 0; mt < 2; mt++)
#pragma unroll
            for (int nt = 0; nt < 4; nt++)
                bmma(acc[mt][nt], ahi[mt], blo[nt >> 1][nt & 1], blo[nt >> 1][(nt & 1) + 2]);
#pragma unroll
        for (int mt = 0; mt < 2; mt++)
#pragma unroll
            for (int nt = 0; nt < 4; nt++)
                bmma(acc[mt][nt], alo[mt], bhi[nt >> 1][nt & 1], bhi[nt >> 1][(nt & 1) + 2]);

        if (c + 1 < KT) STORE((c + 1) & 1);
        __syncthreads();
    }

    // ---- epilogue ----
    // D tile: c0,c1 -> row lane>>2, cols (lane&3)*2,+1 ; c2,c3 -> row+8
    if (MODE == 0) {
        float lsum = 0.f, lsq = 0.f;
#pragma unroll
        for (int mt = 0; mt < 2; mt++) {
            int rbase = row0 + m0 + mt * 16 + (lane >> 2);
#pragma unroll
            for (int half = 0; half < 2; half++) {
                int rr = rbase + half * 8;
                if (rr < N_NODES) {
#pragma unroll
                    for (int nt = 0; nt < 4; nt++) {
                        int col = n0 + nt * 8 + (lane & 3) * 2;
                        float v0 = acc[mt][nt][half * 2]     + sparam[col];
                        float v1 = acc[mt][nt][half * 2 + 1] + sparam[col + 1];
                        lsum += v0 + v1;
                        lsq += v0 * v0 + v1 * v1;
                        *(float2*)(out + (size_t)rr * F + col) = make_float2(v0, v1);
                    }
                }
            }
        }
        rbuf[tid] = make_float2(lsum, lsq);
        __syncthreads();
        for (int s = 256; s > 0; s >>= 1) {
            if (tid < s) {
                rbuf[tid].x += rbuf[tid + s].x;
                rbuf[tid].y += rbuf[tid + s].y;
            }
            __syncthreads();
        }
        if (tid == 0) {
            atomicAdd(&g_stats[stat_ofs], rbuf[0].x);
            atomicAdd(&g_stats[stat_ofs + 1], rbuf[0].y);
        }
    } else {
        float m = g_stats[2];
        float aa = g_stats[3];
        float pww = pw[0];
#pragma unroll
        for (int mt = 0; mt < 2; mt++) {
            int rbase = row0 + m0 + mt * 16 + (lane >> 2);
#pragma unroll
            for (int half = 0; half < 2; half++) {
                int rr = rbase + half * 8;
                if (rr < N_NODES) {
#pragma unroll
                    for (int nt = 0; nt < 4; nt++) {
                        int col = n0 + nt * 8 + (lane & 3) * 2;
                        float2 o = *(const float2*)((const float*)g_o + (size_t)rr * F + col);
                        float t0 = (o.x - m) * aa * sparam[col]     + sparam[F + col];
                        float t1 = (o.y - m) * aa * sparam[col + 1] + sparam[F + col + 1];
                        t0 = (t0 >= 0.f) ? t0 : pww * t0;
                        t1 = (t1 >= 0.f) ? t1 : pww * t1;
                        *(float2*)(out + (size_t)rr * F + col) =
                            make_float2(acc[mt][nt][half * 2] + t0,
                                        acc[mt][nt][half * 2 + 1] + t1);
                    }
                }
            }
        }
    }
#undef LDREGS
#undef STORE
}

// ---------------- LN-stats finalize ----------------
__global__ void finalize_kernel(int ofs) {
    float S = g_stats[ofs], SS = g_stats[ofs + 1];
    float inv = 1.0f / ((float)N_NODES * (float)F);
    float m = S * inv;
    float var = fmaxf(SS * inv - m * m, 0.0f);
    g_stats[ofs + 2] = m;
    g_stats[ofs + 3] = 1.0f / (sqrtf(var) + LN_EPS);
}

// ---------------- final LN + PReLU ----------------
__global__ void apply_kernel(const float* __restrict__ lnw,
                             const float* __restrict__ lnb,
                             const float* __restrict__ pw,
                             float* __restrict__ out) {
    int i = blockIdx.x * blockDim.x + threadIdx.x;
    if (i < N_NODES * F) {
        float m = g_stats[6];
        float a = g_stats[7];
        int col = i & (F - 1);
        float t = (g_o[i] - m) * a * lnw[col] + lnb[col];
        out[i] = (t >= 0.f) ? t : pw[0] * t;
    }
}

// ---------------- launch ----------------
extern "C" void kernel_launch(void* const* d_in, const int* in_sizes, int n_in,
                              void* d_out, int out_size) {
    const float* x      = (const float*)d_in[0];
    const void*  ei     = d_in[1];
    const float* Wl0    = (const float*)d_in[2];
    const float* bl0    = (const float*)d_in[3];
    const float* Wr0    = (const float*)d_in[4];
    const float* lnw0   = (const float*)d_in[5];
    const float* lnb0   = (const float*)d_in[6];
    const float* pw0    = (const float*)d_in[7];
    const float* skipW0 = (const float*)d_in[8];
    const float* Wl1    = (const float*)d_in[9];
    const float* bl1    = (const float*)d_in[10];
    const float* Wr1    = (const float*)d_in[11];
    const float* lnw1   = (const float*)d_in[12];
    const float* lnb1   = (const float*)d_in[13];
    const float* pw1    = (const float*)d_in[14];

    int gblocks = (N_NODES + 127) / 128;                 // 391
    int eblocks = (N_EDGES + 255) / 256;                 // 3125
    int wblocks = (N_NODES * 32 + 255) / 256;            // 6250

    // CSR build (once; reused by both layers)
    detect_kernel<<<1, 256>>>(ei);
    zero_kernel<<<NBLK, 256>>>();
    hist_kernel<<<eblocks, 256>>>(ei);
    scanA_kernel<<<NBLK, 256>>>();
    scanB_kernel<<<1, 256>>>();
    scanC_kernel<<<NBLK, 256>>>();
    fill_kernel<<<eblocks, 256>>>(ei);

    // layer 0
    gather_kernel<<<wblocks, 256>>>(x);
    mmagemm_kernel<0, 16><<<gblocks, 512>>>(x, Wl0, Wr0, bl0, 0,
                                            nullptr, nullptr, nullptr);
    finalize_kernel<<<1, 1>>>(0);

    // h = x @ skipW0^T + prelu(ln(out0))  -> g_h
    mmagemm_kernel<1, 8><<<gblocks, 512>>>(x, skipW0, nullptr, nullptr, 0,
                                           lnw0, lnb0, pw0);

    // layer 1
    gather_kernel<<<wblocks, 256>>>(nullptr);
    mmagemm_kernel<0, 16><<<gblocks, 512>>>(nullptr, Wl1, Wr1, bl1, 4,
                                            nullptr, nullptr, nullptr);
    finalize_kernel<<<1, 1>>>(4);

    apply_kernel<<<(N_NODES * F + 255) / 256, 256>>>(lnw1, lnb1, pw1, (float*)d_out);
}

// round 7
// speedup vs baseline: 1.9981x; 1.0069x over previous
#include <cuda_runtime.h>
#include <cuda_bf16.h>
#include <cstdint>

#define N_NODES 50000
#define N_EDGES 800000
#define F 128
#define LN_EPS 1e-5f
#define NBLK 196            // (N_NODES+255)/256
#define NPAD (N_NODES + 128)
#define SROWB 512           // bytes per split row (8 chunks x [32B hi | 32B lo])

// ---------------- scratch (__device__ globals only) ----------------
__device__ int   g_is64;
__device__ int   g_count[N_NODES];
__device__ int   g_start[N_NODES + 1];
__device__ int   g_cursor[N_NODES];
__device__ int   g_bsum[NBLK];
__device__ int   g_boff[NBLK];
__device__ int   g_esrc[N_EDGES];
__device__ float g_invdeg[N_NODES];
__device__ char  g_ws[5 * 65536];                    // split weights (tile layout)
__device__ char  g_xs[(size_t)NPAD * SROWB];         // split x
__device__ char  g_ms[(size_t)NPAD * SROWB];         // split neighbor-mean
__device__ float g_h[(size_t)NPAD * F];              // layer-1 input (fp32)
__device__ float g_o[(size_t)NPAD * F];              // raw SAGE out (pre-LN)
__device__ float g_stats[8];

// ---------------- helpers ----------------
__device__ __forceinline__ uint32_t s2u(const void* p) {
    uint32_t a;
    asm("{ .reg .u64 t; cvta.to.shared.u64 t, %1; cvt.u32.u64 %0, t; }"
        : "=r"(a) : "l"(p));
    return a;
}
// pack two fp32 -> bf16x2 (a low half, b high half)
__device__ __forceinline__ uint32_t pkbf(float a, float b) {
    uint32_t r;
    asm("cvt.rn.bf16x2.f32 %0, %1, %2;" : "=r"(r) : "f"(b), "f"(a));
    return r;
}
__device__ __forceinline__ void ldsm4(uint32_t addr, uint32_t* r) {
    asm volatile("ldmatrix.sync.aligned.m8n8.x4.shared.b16 {%0,%1,%2,%3}, [%4];"
                 : "=r"(r[0]), "=r"(r[1]), "=r"(r[2]), "=r"(r[3]) : "r"(addr));
}
__device__ __forceinline__ void bmma(float* d, const uint32_t* a, uint32_t b0, uint32_t b1) {
    asm volatile("mma.sync.aligned.m16n8k16.row.col.f32.bf16.bf16.f32 "
                 "{%0,%1,%2,%3}, {%4,%5,%6,%7}, {%8,%9}, {%0,%1,%2,%3};"
                 : "+f"(d[0]), "+f"(d[1]), "+f"(d[2]), "+f"(d[3])
                 : "r"(a[0]), "r"(a[1]), "r"(a[2]), "r"(a[3]), "r"(b0), "r"(b1));
}
// split float4 -> hi/lo uint2 pairs
__device__ __forceinline__ void split4(float4 v, uint2& hi, uint2& lo) {
    float h0 = __bfloat162float(__float2bfloat16_rn(v.x));
    float h1 = __bfloat162float(__float2bfloat16_rn(v.y));
    float h2 = __bfloat162float(__float2bfloat16_rn(v.z));
    float h3 = __bfloat162float(__float2bfloat16_rn(v.w));
    hi = make_uint2(pkbf(h0, h1), pkbf(h2, h3));
    lo = make_uint2(pkbf(v.x - h0, v.y - h1), pkbf(v.z - h2, v.w - h3));
}

// ---------------- index load helper ----------------
__device__ __forceinline__ int ld_idx(const void* ei, long long pos, int is64) {
    if (is64) return (int)((const long long*)ei)[pos];
    return ((const int*)ei)[pos];
}

// ---------------- zero + dtype probe ----------------
__global__ void zerodetect_kernel(const void* ei) {
    int i = blockIdx.x * blockDim.x + threadIdx.x;
    if (i < N_NODES) { g_count[i] = 0; g_cursor[i] = 0; }
    if (blockIdx.x == 0) {
        __shared__ int nz;
        int tid = threadIdx.x;
        if (tid == 0) nz = 0;
        __syncthreads();
        int v = ((const int*)ei)[2 * tid + 1];
        if (v != 0) atomicAdd(&nz, 1);
        __syncthreads();
        if (tid == 0) g_is64 = (nz == 0) ? 1 : 0;
        if (tid < 8) g_stats[tid] = 0.0f;
    }
}

__global__ void hist_kernel(const void* ei) {
    int e = blockIdx.x * blockDim.x + threadIdx.x;
    if (e < N_EDGES) {
        int d = ld_idx(ei, (long long)N_EDGES + e, g_is64);
        atomicAdd(&g_count[d], 1);
    }
}

// ---------------- multi-block scan ----------------
__global__ void scanA_kernel() {
    __shared__ int sh[256];
    int i = blockIdx.x * 256 + threadIdx.x;
    int c = (i < N_NODES) ? g_count[i] : 0;
    sh[threadIdx.x] = c;
    __syncthreads();
#pragma unroll
    for (int s = 128; s > 0; s >>= 1) {
        if (threadIdx.x < s) sh[threadIdx.x] += sh[threadIdx.x + s];
        __syncthreads();
    }
    if (threadIdx.x == 0) g_bsum[blockIdx.x] = sh[0];
}

__global__ void scanB_kernel() {
    __shared__ int sh[256];
    int t = threadIdx.x;
    int v = (t < NBLK) ? g_bsum[t] : 0;
    sh[t] = v;
    __syncthreads();
#pragma unroll
    for (int off = 1; off < 256; off <<= 1) {
        int u = (t >= off) ? sh[t - off] : 0;
        __syncthreads();
        sh[t] += u;
        __syncthreads();
    }
    if (t < NBLK) g_boff[t] = sh[t] - v;
    if (t == 0) g_start[N_NODES] = N_EDGES;
}

__global__ void scanC_kernel() {
    __shared__ int sh[256];
    int t = threadIdx.x;
    int i = blockIdx.x * 256 + t;
    int c = (i < N_NODES) ? g_count[i] : 0;
    sh[t] = c;
    __syncthreads();
#pragma unroll
    for (int off = 1; off < 256; off <<= 1) {
        int u = (t >= off) ? sh[t - off] : 0;
        __syncthreads();
        sh[t] += u;
        __syncthreads();
    }
    if (i < N_NODES) {
        g_start[i] = sh[t] - c + g_boff[blockIdx.x];
        g_invdeg[i] = 1.0f / fmaxf((float)c, 1.0f);
    }
}

__global__ void fill_kernel(const void* ei) {
    int e = blockIdx.x * blockDim.x + threadIdx.x;
    if (e < N_EDGES) {
        int is64 = g_is64;
        int d = ld_idx(ei, (long long)N_EDGES + e, is64);
        int s = ld_idx(ei, (long long)e, is64);
        int pos = atomicAdd(&g_cursor[d], 1);
        g_esrc[g_start[d] + pos] = s;
    }
}

// ---------------- weight pre-split: 5 matrices -> tile-layout split ----------------
__global__ void wprep_kernel(const float* __restrict__ W0, const float* __restrict__ W1,
                             const float* __restrict__ W2, const float* __restrict__ W3,
                             const float* __restrict__ W4) {
    int t = blockIdx.x * 256 + threadIdx.x;        // < 20480
    int mat = t >> 12;                             // 4096 threads per matrix
    int rem = t & 4095;
    int row = rem >> 5, lane = rem & 31;
    const float* W = (mat == 0) ? W0 : (mat == 1) ? W1 : (mat == 2) ? W2
                     : (mat == 3) ? W3 : W4;
    float4 v = *(const float4*)(W + row * F + lane * 4);
    uint2 hi, lo;
    split4(v, hi, lo);
    char* dst = g_ws + (size_t)mat * 65536 + row * SROWB + (lane >> 2) * 64 + (lane & 3) * 8;
    *(uint2*)dst = hi;
    *(uint2*)(dst + 32) = lo;
}

// ---------------- x pre-split ----------------
__global__ void xprep_kernel(const float* __restrict__ x) {
    int t = blockIdx.x * 256 + threadIdx.x;
    int row = t >> 5, lane = t & 31;
    if (row < N_NODES) {
        float4 v = *(const float4*)(x + (size_t)row * F + lane * 4);
        uint2 hi, lo;
        split4(v, hi, lo);
        char* dst = g_xs + (size_t)row * SROWB + (lane >> 2) * 64 + (lane & 3) * 8;
        *(uint2*)dst = hi;
        *(uint2*)(dst + 32) = lo;
    }
}

// ---------------- gather-mean: warp per node, emits split form ----------------
__global__ void gather_kernel(const float* __restrict__ hin) {
    const float* h = hin ? hin : (const float*)g_h;
    int n = (blockIdx.x * blockDim.x + threadIdx.x) >> 5;
    int lane = threadIdx.x & 31;
    if (n >= N_NODES) return;
    int e = g_start[n];
    int end = g_start[n + 1];
    float4 acc0 = make_float4(0.f, 0.f, 0.f, 0.f);
    float4 acc1 = make_float4(0.f, 0.f, 0.f, 0.f);
    for (; e + 1 < end; e += 2) {
        int s0 = g_esrc[e];
        int s1 = g_esrc[e + 1];
        float4 v0 = *(const float4*)(h + (size_t)s0 * F + lane * 4);
        float4 v1 = *(const float4*)(h + (size_t)s1 * F + lane * 4);
        acc0.x += v0.x; acc0.y += v0.y; acc0.z += v0.z; acc0.w += v0.w;
        acc1.x += v1.x; acc1.y += v1.y; acc1.z += v1.z; acc1.w += v1.w;
    }
    if (e < end) {
        int s0 = g_esrc[e];
        float4 v0 = *(const float4*)(h + (size_t)s0 * F + lane * 4);
        acc0.x += v0.x; acc0.y += v0.y; acc0.z += v0.z; acc0.w += v0.w;
    }
    float id = g_invdeg[n];
    acc0.x = (acc0.x + acc1.x) * id;
    acc0.y = (acc0.y + acc1.y) * id;
    acc0.z = (acc0.z + acc1.z) * id;
    acc0.w = (acc0.w + acc1.w) * id;
    uint2 hi, lo;
    split4(acc0, hi, lo);
    char* dst = g_ms + (size_t)n * SROWB + (lane >> 2) * 64 + (lane & 3) * 8;
    *(uint2*)dst = hi;
    *(uint2*)(dst + 32) = lo;
}

// ---------------- mma.sync fused GEMM (pre-split sources) ----------------
// MODE 0: g_o = mean@W0^T + bias + right@W1^T  (K=256, KT=16) + LN-stat sums
//         left = g_ms (split). right: RCVT ? cvt-from-g_h : g_xs (split)
// MODE 1: g_h = xs@W0^T + prelu(ln(g_o))       (K=128, KT=8); inline finalize
#define PITCHB 80

template<int MODE, int KT, int RCVT>
__global__ void __launch_bounds__(512) mmagemm_kernel(
    int W0I, int W1I,
    const float* __restrict__ bias,
    int stat_ofs,
    const float* __restrict__ lnw,
    const float* __restrict__ lnb,
    const float* __restrict__ pw)
{
    __shared__ __align__(16) char smA[2][128 * PITCHB];
    __shared__ __align__(16) char smB[2][128 * PITCHB];
    __shared__ float sparam[2 * F];
    __shared__ float2 rbuf[512];

    float* out = (MODE == 0) ? (float*)g_o : (float*)g_h;

    int tid = threadIdx.x;
    int lane = tid & 31;
    int w = tid >> 5;
    int row0 = blockIdx.x * 128;

    if (tid < F) {
        if (MODE == 0) sparam[tid] = bias[tid];
        else { sparam[tid] = lnw[tid]; sparam[F + tid] = lnb[tid]; }
    }

    int srow = tid >> 2;              // 0..127
    int q = tid & 3;                  // 16B part / col-quad
    size_t arow512 = (size_t)(row0 + srow) * SROWB;
    size_t brow512 = (size_t)srow * SROWB;
    const float* Af = (const float*)g_h + (size_t)(row0 + srow) * F;  // cvt source

    float acc[2][4][4];
#pragma unroll
    for (int i = 0; i < 2; i++)
#pragma unroll
        for (int j = 0; j < 4; j++)
#pragma unroll
            for (int k = 0; k < 4; k++) acc[i][j][k] = 0.0f;

    uint4 av4, bv4;
    float4 afv;

#define LDREGS(c)                                                              \
    {                                                                          \
        int cc = (c);                                                          \
        if (MODE == 0 && RCVT && cc >= 8) {                                    \
            afv = *(const float4*)(Af + (cc - 8) * 16 + q * 4);                \
        } else {                                                               \
            const char* ap;                                                    \
            if (MODE == 0 && cc < 8) ap = g_ms + arow512 + cc * 64 + q * 16;   \
            else {                                                             \
                int c2 = (MODE == 0) ? cc - 8 : cc;                            \
                ap = g_xs + arow512 + c2 * 64 + q * 16;                        \
            }                                                                  \
            av4 = *(const uint4*)ap;                                           \
        }                                                                      \
        int widx, wc;                                                          \
        if (MODE == 0 && cc >= 8) { widx = W1I; wc = cc - 8; }                 \
        else { widx = W0I; wc = cc; }                                          \
        bv4 = *(const uint4*)(g_ws + (size_t)widx * 65536 + brow512 +          \
                              wc * 64 + q * 16);                               \
    }

#define STORE(b, c)                                                            \
    {                                                                          \
        int cc = (c);                                                          \
        if (MODE == 0 && RCVT && cc >= 8) {                                    \
            uint2 hi, lo;                                                      \
            split4(afv, hi, lo);                                               \
            char* ab = smA[b] + srow * PITCHB + q * 8;                         \
            *(uint2*)ab = hi;                                                  \
            *(uint2*)(ab + 32) = lo;                                           \
        } else {                                                               \
            *(uint4*)(smA[b] + srow * PITCHB + q * 16) = av4;                  \
        }                                                                      \
        *(uint4*)(smB[b] + srow * PITCHB + q * 16) = bv4;                      \
    }

    LDREGS(0);
    STORE(0, 0);
    __syncthreads();

    int wm = w >> 2, wn = w & 3;
    int m0 = wm * 32, n0 = wn * 32;
    uint32_t rsel = (uint32_t)(lane & 15);
    uint32_t kb = (uint32_t)((lane >> 4) * 16);

    for (int c = 0; c < KT; c++) {
        if (c + 1 < KT) LDREGS(c + 1);

        int b = c & 1;
        uint32_t Ab = s2u(smA[b]);
        uint32_t Bb = s2u(smB[b]);
        uint32_t aaddr0 = Ab + (m0 + rsel) * PITCHB + kb;
        uint32_t aaddr1 = aaddr0 + 16 * PITCHB;
        uint32_t baddr0 = Bb + (n0 + rsel) * PITCHB + kb;
        uint32_t baddr1 = baddr0 + 16 * PITCHB;

        uint32_t ahi[2][4], alo[2][4], bhi[2][4], blo[2][4];
        ldsm4(aaddr0, ahi[0]);  ldsm4(aaddr1, ahi[1]);
        ldsm4(baddr0, bhi[0]);  ldsm4(baddr1, bhi[1]);
        ldsm4(aaddr0 + 32, alo[0]);  ldsm4(aaddr1 + 32, alo[1]);
        ldsm4(baddr0 + 32, blo[0]);  ldsm4(baddr1 + 32, blo[1]);

#pragma unroll
        for (int mt = 0; mt < 2; mt++)
#pragma unroll
            for (int nt = 0; nt < 4; nt++)
                bmma(acc[mt][nt], ahi[mt], bhi[nt >> 1][nt & 1], bhi[nt >> 1][(nt & 1) + 2]);
#pragma unroll
        for (int mt = 0; mt < 2; mt++)
#pragma unroll
            for (int nt = 0; nt < 4; nt++)
                bmma(acc[mt][nt], ahi[mt], blo[nt >> 1][nt & 1], blo[nt >> 1][(nt & 1) + 2]);
#pragma unroll
        for (int mt = 0; mt < 2; mt++)
#pragma unroll
            for (int nt = 0; nt < 4; nt++)
                bmma(acc[mt][nt], alo[mt], bhi[nt >> 1][nt & 1], bhi[nt >> 1][(nt & 1) + 2]);

        if (c + 1 < KT) STORE((c + 1) & 1, c + 1);
        __syncthreads();
    }

    // ---- epilogue ----
    if (MODE == 0) {
        float lsum = 0.f, lsq = 0.f;
#pragma unroll
        for (int mt = 0; mt < 2; mt++) {
            int rbase = row0 + m0 + mt * 16 + (lane >> 2);
#pragma unroll
            for (int half = 0; half < 2; half++) {
                int rr = rbase + half * 8;
                if (rr < N_NODES) {
#pragma unroll
                    for (int nt = 0; nt < 4; nt++) {
                        int col = n0 + nt * 8 + (lane & 3) * 2;
                        float v0 = acc[mt][nt][half * 2]     + sparam[col];
                        float v1 = acc[mt][nt][half * 2 + 1] + sparam[col + 1];
                        lsum += v0 + v1;
                        lsq += v0 * v0 + v1 * v1;
                        *(float2*)(out + (size_t)rr * F + col) = make_float2(v0, v1);
                    }
                }
            }
        }
        rbuf[tid] = make_float2(lsum, lsq);
        __syncthreads();
        for (int s = 256; s > 0; s >>= 1) {
            if (tid < s) {
                rbuf[tid].x += rbuf[tid + s].x;
                rbuf[tid].y += rbuf[tid + s].y;
            }
            __syncthreads();
        }
        if (tid == 0) {
            atomicAdd(&g_stats[stat_ofs], rbuf[0].x);
            atomicAdd(&g_stats[stat_ofs + 1], rbuf[0].y);
        }
    } else {
        // inline finalize from accumulated sums
        float S = g_stats[0], SS = g_stats[1];
        float inv = 1.0f / ((float)N_NODES * (float)F);
        float m = S * inv;
        float var = fmaxf(SS * inv - m * m, 0.0f);
        float aa = 1.0f / (sqrtf(var) + LN_EPS);
        float pww = pw[0];
#pragma unroll
        for (int mt = 0; mt < 2; mt++) {
            int rbase = row0 + m0 + mt * 16 + (lane >> 2);
#pragma unroll
            for (int half = 0; half < 2; half++) {
                int rr = rbase + half * 8;
                if (rr < N_NODES) {
#pragma unroll
                    for (int nt = 0; nt < 4; nt++) {
                        int col = n0 + nt * 8 + (lane & 3) * 2;
                        float2 o = *(const float2*)((const float*)g_o + (size_t)rr * F + col);
                        float t0 = (o.x - m) * aa * sparam[col]     + sparam[F + col];
                        float t1 = (o.y - m) * aa * sparam[col + 1] + sparam[F + col + 1];
                        t0 = (t0 >= 0.f) ? t0 : pww * t0;
                        t1 = (t1 >= 0.f) ? t1 : pww * t1;
                        *(float2*)(out + (size_t)rr * F + col) =
                            make_float2(acc[mt][nt][half * 2] + t0,
                                        acc[mt][nt][half * 2 + 1] + t1);
                    }
                }
            }
        }
    }
#undef LDREGS
#undef STORE
}

// ---------------- final LN + PReLU (inline finalize) ----------------
__global__ void apply_kernel(const float* __restrict__ lnw,
                             const float* __restrict__ lnb,
                             const float* __restrict__ pw,
                             float* __restrict__ out) {
    int i = blockIdx.x * blockDim.x + threadIdx.x;
    if (i < N_NODES * F) {
        float S = g_stats[4], SS = g_stats[5];
        float inv = 1.0f / ((float)N_NODES * (float)F);
        float m = S * inv;
        float var = fmaxf(SS * inv - m * m, 0.0f);
        float a = 1.0f / (sqrtf(var) + LN_EPS);
        int col = i & (F - 1);
        float t = (g_o[i] - m) * a * lnw[col] + lnb[col];
        out[i] = (t >= 0.f) ? t : pw[0] * t;
    }
}

// ---------------- launch ----------------
extern "C" void kernel_launch(void* const* d_in, const int* in_sizes, int n_in,
                              void* d_out, int out_size) {
    const float* x      = (const float*)d_in[0];
    const void*  ei     = d_in[1];
    const float* Wl0    = (const float*)d_in[2];
    const float* bl0    = (const float*)d_in[3];
    const float* Wr0    = (const float*)d_in[4];
    const float* lnw0   = (const float*)d_in[5];
    const float* lnb0   = (const float*)d_in[6];
    const float* pw0    = (const float*)d_in[7];
    const float* skipW0 = (const float*)d_in[8];
    const float* Wl1    = (const float*)d_in[9];
    const float* bl1    = (const float*)d_in[10];
    const float* Wr1    = (const float*)d_in[11];
    const float* lnw1   = (const float*)d_in[12];
    const float* lnb1   = (const float*)d_in[13];
    const float* pw1    = (const float*)d_in[14];

    int gblocks = (N_NODES + 127) / 128;                 // 391
    int eblocks = (N_EDGES + 255) / 256;                 // 3125
    int wblocks = (N_NODES * 32 + 255) / 256;            // 6250

    // CSR build + pre-splits
    zerodetect_kernel<<<NBLK, 256>>>(ei);
    wprep_kernel<<<80, 256>>>(Wl0, Wr0, skipW0, Wl1, Wr1);
    xprep_kernel<<<wblocks, 256>>>(x);
    hist_kernel<<<eblocks, 256>>>(ei);
    scanA_kernel<<<NBLK, 256>>>();
    scanB_kernel<<<1, 256>>>();
    scanC_kernel<<<NBLK, 256>>>();
    fill_kernel<<<eblocks, 256>>>(ei);

    // layer 0
    gather_kernel<<<wblocks, 256>>>(x);
    mmagemm_kernel<0, 16, 0><<<gblocks, 512>>>(0, 1, bl0, 0,
                                               nullptr, nullptr, nullptr);
    // h = x @ skipW0^T + prelu(ln(g_o))  -> g_h  (finalize inlined)
    mmagemm_kernel<1, 8, 0><<<gblocks, 512>>>(2, 2, nullptr, 0,
                                              lnw0, lnb0, pw0);
    // layer 1
    gather_kernel<<<wblocks, 256>>>(nullptr);            // reads g_h
    mmagemm_kernel<0, 16, 1><<<gblocks, 512>>>(3, 4, bl1, 4,
                                               nullptr, nullptr, nullptr);
    apply_kernel<<<(N_NODES * F + 255) / 256, 256>>>(lnw1, lnb1, pw1, (float*)d_out);
}